// round 6
// baseline (speedup 1.0000x reference)
#include <cuda_runtime.h>
#include <stdint.h>

#define NN 8192

// Scratch (device globals — no allocations allowed)
__device__ int   g_idx[NN];      // compacted indices of nonzero eps
__device__ float g_epsval[NN];   // compacted eps values
__device__ int   g_nnz;

__global__ void k_reset() { g_nnz = 0; }

// Pre-pass: eps sparsity compaction only.
__global__ void k_pre(const float* __restrict__ ts,
                      const float* __restrict__ tau_s)
{
    int i = blockIdx.x * blockDim.x + threadIdx.x;
    if (i >= NN) return;

    // eps = (1 + tanh(t)) * exp(-t/tau_s) / tau_s,  t = ts - 1
    float t    = ts[i] - 1.0f;
    float taus = tau_s[i];
    float eps  = (1.0f + tanhf(t)) * expf(-t / taus) / taus;
    if (eps != 0.0f) {
        int p = atomicAdd(&g_nnz, 1);
        g_idx[p]    = i;
        g_epsval[p] = eps;
    }
}

// Threefry-2x32-20, key=(0,42), partitionable path: counter = (hi32(i), lo32(i)),
// 32-bit output = o1 ^ o2.  (jax_threefry_partitionable=True default)
__device__ __forceinline__ uint32_t threefry_bits_partitionable(uint32_t i)
{
    const uint32_t ks0 = 0u;
    const uint32_t ks1 = 42u;
    const uint32_t ks2 = 0x1BD11BDAu ^ ks0 ^ ks1;
    uint32_t x0 = 0u + ks0;   // hi 32 bits of uint64 counter i (i < 2^32)
    uint32_t x1 = i  + ks1;   // lo 32 bits
    #define TF_RND(r) { x0 += x1; x1 = (x1 << (r)) | (x1 >> (32 - (r))); x1 ^= x0; }
    TF_RND(13) TF_RND(15) TF_RND(26) TF_RND(6)
    x0 += ks1; x1 += ks2 + 1u;
    TF_RND(17) TF_RND(29) TF_RND(16) TF_RND(24)
    x0 += ks2; x1 += ks0 + 2u;
    TF_RND(13) TF_RND(15) TF_RND(26) TF_RND(6)
    x0 += ks0; x1 += ks1 + 3u;
    TF_RND(17) TF_RND(29) TF_RND(16) TF_RND(24)
    x0 += ks1; x1 += ks2 + 4u;
    TF_RND(13) TF_RND(15) TF_RND(26) TF_RND(6)
    x0 += ks2; x1 += ks0 + 5u;
    #undef TF_RND
    return x0 ^ x1;           // bits1 ^ bits2 (bit_width==32 combine)
}

// Warp-per-row sparse-gather matvec (over nonzero eps columns) + fused epilogue
// (theta update + membrane update + lambda + threefry bernoulli + reset).
__global__ void k_main(const float* __restrict__ w,
                       const float* __restrict__ v,
                       const float* __restrict__ I_ext,
                       const float* __restrict__ E_L,
                       const float* __restrict__ tau_m,
                       const float* __restrict__ ts,
                       const float* __restrict__ c,
                       const float* __restrict__ Delta_u,
                       const float* __restrict__ theta_v,
                       const float* __restrict__ theta_inf,
                       const float* __restrict__ J_theta,
                       const float* __restrict__ spiked,
                       const float* __restrict__ tau_theta,
                       float* __restrict__ out)
{
    int gwarp = (blockIdx.x * blockDim.x + threadIdx.x) >> 5;
    int lane  = threadIdx.x & 31;
    if (gwarp >= NN) return;
    int row = gwarp;

    int nnz = g_nnz;
    float acc = 0.0f;
    const float* wrow = w + (size_t)row * NN;
    for (int j = lane; j < nnz; j += 32) {
        int col = g_idx[j];
        float we = (col == row) ? 0.0f : wrow[col];  // zero diagonal (no self-recurrence)
        acc += we * g_epsval[j];
    }
    #pragma unroll
    for (int off = 16; off > 0; off >>= 1)
        acc += __shfl_down_sync(0xFFFFFFFFu, acc, off);

    if (lane == 0) {
        // adaptation threshold update (row-local)
        float th = theta_v[row]
                 + (theta_inf[row] - theta_v[row] + J_theta[row] * spiked[row]) / tau_theta[row];

        float vi     = v[row];
        float v_next = vi + (E_L[row] - vi + I_ext[row]) / tau_m[row] + acc;
        float notref = (ts[row] > 2.0f) ? 1.0f : 0.0f;
        float lam    = notref * c[row] * expf((v_next - th) / Delta_u[row]);
        lam = fminf(fmaxf(lam, 0.0f), 1.0f);

        // JAX uniform: bitcast((bits >> 9) | 0x3F800000) - 1.0 ; bernoulli = u < p
        uint32_t bits = threefry_bits_partitionable((uint32_t)row);
        float u  = __uint_as_float((bits >> 9) | 0x3F800000u) - 1.0f;
        float sp = (u < lam) ? 1.0f : 0.0f;

        out[row]          = lam;                   // spikes_lambda
        out[NN + row]     = sp;                    // spiked_new
        out[2 * NN + row] = (1.0f - sp) * v_next;  // v_new (reset potential = 0)
    }
}

extern "C" void kernel_launch(void* const* d_in, const int* in_sizes, int n_in,
                              void* d_out, int out_size)
{
    // metadata order = setup_inputs dict order
    const float* I_ext     = (const float*)d_in[0];
    const float* w         = (const float*)d_in[1];
    const float* v         = (const float*)d_in[2];
    const float* spiked    = (const float*)d_in[3];
    const float* ts        = (const float*)d_in[4];
    const float* theta_v   = (const float*)d_in[5];
    const float* tau_m     = (const float*)d_in[6];
    const float* tau_s     = (const float*)d_in[7];
    const float* tau_theta = (const float*)d_in[8];
    const float* J_theta   = (const float*)d_in[9];
    const float* E_L       = (const float*)d_in[10];
    const float* c         = (const float*)d_in[11];
    const float* Delta_u   = (const float*)d_in[12];
    const float* theta_inf = (const float*)d_in[13];
    float* out = (float*)d_out;

    k_reset<<<1, 1>>>();
    k_pre<<<NN / 256, 256>>>(ts, tau_s);
    k_main<<<(NN * 32) / 256, 256>>>(w, v, I_ext, E_L, tau_m, ts, c, Delta_u,
                                     theta_v, theta_inf, J_theta, spiked, tau_theta, out);
}

// round 7
// speedup vs baseline: 1.0669x; 1.0669x over previous
#include <cuda_runtime.h>
#include <stdint.h>

#define NN 8192
#define PRE_BLOCKS 32
#define PRE_THREADS 256

// Scratch (device globals — no allocations). Reset-free: per-block segments
// overwritten by plain stores every launch.
__device__ int   g_idx[NN];        // compacted nonzero-eps indices, segmented per pre-block
__device__ float g_epsval[NN];     // compacted eps values, same segmentation
__device__ int   g_cnt[PRE_BLOCKS]; // per-block nonzero count (plain store each launch)

// Pre-pass: eps + per-block compaction (no global reset needed).
__global__ void k_pre(const float* __restrict__ ts,
                      const float* __restrict__ tau_s)
{
    __shared__ int s_cnt;
    if (threadIdx.x == 0) s_cnt = 0;
    __syncthreads();

    int i = blockIdx.x * PRE_THREADS + threadIdx.x;

    // eps = (1 + tanh(t)) * exp(-t/tau_s) / tau_s,  t = ts - 1
    float t    = ts[i] - 1.0f;
    float taus = tau_s[i];
    float eps  = (1.0f + tanhf(t)) * expf(-t / taus) / taus;
    if (eps != 0.0f) {
        int p = atomicAdd(&s_cnt, 1);
        int base = blockIdx.x * PRE_THREADS;
        g_idx[base + p]    = i;
        g_epsval[base + p] = eps;
    }
    __syncthreads();
    if (threadIdx.x == 0) g_cnt[blockIdx.x] = s_cnt;  // plain store: overwrite, no reset
}

// Threefry-2x32-20, key=(0,42), partitionable path: counter=(hi32,lo32)=(0,i),
// 32-bit output = o1 ^ o2.
__device__ __forceinline__ uint32_t threefry_bits_partitionable(uint32_t i)
{
    const uint32_t ks0 = 0u;
    const uint32_t ks1 = 42u;
    const uint32_t ks2 = 0x1BD11BDAu ^ ks0 ^ ks1;
    uint32_t x0 = 0u + ks0;
    uint32_t x1 = i  + ks1;
    #define TF_RND(r) { x0 += x1; x1 = (x1 << (r)) | (x1 >> (32 - (r))); x1 ^= x0; }
    TF_RND(13) TF_RND(15) TF_RND(26) TF_RND(6)
    x0 += ks1; x1 += ks2 + 1u;
    TF_RND(17) TF_RND(29) TF_RND(16) TF_RND(24)
    x0 += ks2; x1 += ks0 + 2u;
    TF_RND(13) TF_RND(15) TF_RND(26) TF_RND(6)
    x0 += ks0; x1 += ks1 + 3u;
    TF_RND(17) TF_RND(29) TF_RND(16) TF_RND(24)
    x0 += ks1; x1 += ks2 + 4u;
    TF_RND(13) TF_RND(15) TF_RND(26) TF_RND(6)
    x0 += ks2; x1 += ks0 + 5u;
    #undef TF_RND
    return x0 ^ x1;
}

// Warp-per-row sparse-gather matvec over nonzero-eps segments + fused epilogue.
__global__ void k_main(const float* __restrict__ w,
                       const float* __restrict__ v,
                       const float* __restrict__ I_ext,
                       const float* __restrict__ E_L,
                       const float* __restrict__ tau_m,
                       const float* __restrict__ ts,
                       const float* __restrict__ c,
                       const float* __restrict__ Delta_u,
                       const float* __restrict__ theta_v,
                       const float* __restrict__ theta_inf,
                       const float* __restrict__ J_theta,
                       const float* __restrict__ spiked,
                       const float* __restrict__ tau_theta,
                       float* __restrict__ out)
{
    int gwarp = (blockIdx.x * blockDim.x + threadIdx.x) >> 5;
    int lane  = threadIdx.x & 31;
    if (gwarp >= NN) return;
    int row = gwarp;

    // Lane-parallel read of all 32 per-block counts; skip gather if all zero.
    int mycnt = g_cnt[lane];  // PRE_BLOCKS == 32
    unsigned nz_mask = __ballot_sync(0xFFFFFFFFu, mycnt != 0);

    float acc = 0.0f;
    if (nz_mask) {
        const float* wrow = w + (size_t)row * NN;
        unsigned m = nz_mask;
        while (m) {
            int b = __ffs(m) - 1;
            m &= m - 1;
            int cnt  = __shfl_sync(0xFFFFFFFFu, mycnt, b);
            int base = b * PRE_THREADS;
            for (int j = lane; j < cnt; j += 32) {
                int col = g_idx[base + j];
                float we = (col == row) ? 0.0f : wrow[col];  // mask self-recurrence
                acc += we * g_epsval[base + j];
            }
        }
        #pragma unroll
        for (int off = 16; off > 0; off >>= 1)
            acc += __shfl_down_sync(0xFFFFFFFFu, acc, off);
    }

    if (lane == 0) {
        // adaptation threshold update
        float th = theta_v[row]
                 + (theta_inf[row] - theta_v[row] + J_theta[row] * spiked[row]) / tau_theta[row];

        float vi     = v[row];
        float v_next = vi + (E_L[row] - vi + I_ext[row]) / tau_m[row] + acc;
        float notref = (ts[row] > 2.0f) ? 1.0f : 0.0f;
        float lam    = notref * c[row] * expf((v_next - th) / Delta_u[row]);
        lam = fminf(fmaxf(lam, 0.0f), 1.0f);

        // JAX uniform: bitcast((bits >> 9) | 0x3F800000) - 1.0 ; bernoulli = u < p
        uint32_t bits = threefry_bits_partitionable((uint32_t)row);
        float u  = __uint_as_float((bits >> 9) | 0x3F800000u) - 1.0f;
        float sp = (u < lam) ? 1.0f : 0.0f;

        out[row]          = lam;                   // spikes_lambda
        out[NN + row]     = sp;                    // spiked_new
        out[2 * NN + row] = (1.0f - sp) * v_next;  // v_new (reset = 0)
    }
}

extern "C" void kernel_launch(void* const* d_in, const int* in_sizes, int n_in,
                              void* d_out, int out_size)
{
    const float* I_ext     = (const float*)d_in[0];
    const float* w         = (const float*)d_in[1];
    const float* v         = (const float*)d_in[2];
    const float* spiked    = (const float*)d_in[3];
    const float* ts        = (const float*)d_in[4];
    const float* theta_v   = (const float*)d_in[5];
    const float* tau_m     = (const float*)d_in[6];
    const float* tau_s     = (const float*)d_in[7];
    const float* tau_theta = (const float*)d_in[8];
    const float* J_theta   = (const float*)d_in[9];
    const float* E_L       = (const float*)d_in[10];
    const float* c         = (const float*)d_in[11];
    const float* Delta_u   = (const float*)d_in[12];
    const float* theta_inf = (const float*)d_in[13];
    float* out = (float*)d_out;

    k_pre<<<PRE_BLOCKS, PRE_THREADS>>>(ts, tau_s);
    k_main<<<(NN * 32) / 256, 256>>>(w, v, I_ext, E_L, tau_m, ts, c, Delta_u,
                                     theta_v, theta_inf, J_theta, spiked, tau_theta, out);
}